// round 3
// baseline (speedup 1.0000x reference)
#include <cuda_runtime.h>

#define OUT_STRIDE 896
#define PW0f 0.08838834764831845f
#define INV_SQRT3f 0.5773502691896258f

typedef unsigned long long u64t;

__device__ __forceinline__ u64t ffma2(u64t a, u64t b, u64t c) {
    u64t d;
    asm("fma.rn.f32x2 %0, %1, %2, %3;" : "=l"(d) : "l"(a), "l"(b), "l"(c));
    return d;
}
__device__ __forceinline__ float hsum2(u64t a) {
    return __uint_as_float((unsigned)a) + __uint_as_float((unsigned)(a >> 32));
}

// ===========================================================================
// Kernel A: o0 (cols 0..319)
//   L[r][0:64]  = s_a * s0
//   L[r][64:128]= dot(v_b, v1)/sqrt3
//   o0 = PW0 * (L @ [Wa0; Wb1o0]) + bias
// 512 threads, 1 block/SM. Weights transposed in smem: sWT[col][k] pad 132.
// Thread tile: tx in [0,64) -> cols {tx+64c, c<5}; ty in [0,8) -> 8 rows.
// Chunk = 64 rows. f32x2 packed over k.
// ===========================================================================
#define A_RT 64
#define A_SWT   (320 * 132)                    // 42240
#define A_SL    (A_SWT)                        // sL at 42240, 64*128
#define A_SBIAS (A_SWT + 64 * 128)             // 50432
#define A_SI2   (A_SBIAS + 320)                // 50752
#define A_SMEM_FLOATS (A_SI2 + A_RT * 4)
#define A_SMEM_BYTES  (A_SMEM_FLOATS * 4)

__global__ __launch_bounds__(512, 1) void k_o0(
    const float* __restrict__ in1, const float* __restrict__ in2,
    const float* __restrict__ Wa0, const float* __restrict__ Wb1,
    const float* __restrict__ bias, float* __restrict__ out,
    int n, int nChunks)
{
    extern __shared__ float sm[];
    float* sWT   = sm;
    float* sL    = sm + A_SL;
    float* sBias = sm + A_SBIAS;
    float* sI2   = sm + A_SI2;

    const int tid = threadIdx.x;

    // Stage weights transposed: sWT[col*132 + k], k in [0,128): rows 0..63 Wa0, 64..127 Wb1
    for (int idx = tid; idx < 64 * 320; idx += 512) {
        int u = idx / 320, col = idx - u * 320;
        sWT[col * 132 + u]      = Wa0[idx];
        sWT[col * 132 + 64 + u] = Wb1[idx];
    }
    for (int idx = tid; idx < 320; idx += 512) sBias[idx] = bias[idx];

    const int tx = tid & 63;
    const int ty = tid >> 6;

    for (int chunk = blockIdx.x; chunk < nChunks; chunk += gridDim.x) {
        const int row0 = chunk * A_RT;
        __syncthreads();

        if (tid < A_RT * 4) {
            int r = tid >> 2, c = tid & 3;
            int nr = row0 + r;
            sI2[tid] = (nr < n) ? in2[nr * 4 + c] : 0.f;
        }
        __syncthreads();

        // Stage activations
        {
            const int u  = tid & 63;
            const int rb = tid >> 6;
            #pragma unroll
            for (int i = 0; i < 8; i++) {
                int r  = rb + 8 * i;
                int nr = row0 + r;
                if (nr < n) {
                    const float* ip = in1 + (size_t)nr * 256;
                    float s0 = sI2[r*4+0], vx = sI2[r*4+1], vy = sI2[r*4+2], vz = sI2[r*4+3];
                    float sa = ip[u];
                    float b0 = ip[64 + 3*u], b1 = ip[65 + 3*u], b2 = ip[66 + 3*u];
                    sL[r*128 + u]      = sa * s0;
                    sL[r*128 + 64 + u] = (b0*vx + b1*vy + b2*vz) * INV_SQRT3f;
                } else {
                    sL[r*128 + u] = 0.f;
                    sL[r*128 + 64 + u] = 0.f;
                }
            }
        }
        __syncthreads();

        u64t acc[8][5];
        #pragma unroll
        for (int ri = 0; ri < 8; ri++)
            #pragma unroll
            for (int c = 0; c < 5; c++) acc[ri][c] = 0ull;

        #pragma unroll 2
        for (int kk = 0; kk < 128; kk += 4) {
            ulonglong2 w[5];
            #pragma unroll
            for (int c = 0; c < 5; c++)
                w[c] = *reinterpret_cast<const ulonglong2*>(sWT + (tx + 64*c) * 132 + kk);
            #pragma unroll
            for (int ri = 0; ri < 8; ri++) {
                ulonglong2 a = *reinterpret_cast<const ulonglong2*>(sL + (ty*8 + ri) * 128 + kk);
                #pragma unroll
                for (int c = 0; c < 5; c++) {
                    acc[ri][c] = ffma2(a.x, w[c].x, acc[ri][c]);
                    acc[ri][c] = ffma2(a.y, w[c].y, acc[ri][c]);
                }
            }
        }

        #pragma unroll
        for (int ri = 0; ri < 8; ri++) {
            int nr = row0 + ty*8 + ri;
            if (nr >= n) continue;
            float* op = out + (size_t)nr * OUT_STRIDE;
            #pragma unroll
            for (int c = 0; c < 5; c++) {
                int col = tx + 64*c;
                op[col] = PW0f * hsum2(acc[ri][c]) + sBias[col];
            }
        }
    }
}

// ===========================================================================
// Kernel B: o1 (cols 320..703), o2 (cols 704..895). Chunk = 32 rows.
// Three GEMMs over u (contraction 64), f32x2 packed over u:
//   G1: A[32][128]  = sa  @ Wa1     (stage A to smem)
//   G2: B[96][128]  = vb  @ Wb0, epilogue: o1 = PW0*(A*v1 + B*s0)
//   G3: C[96][64]   = cr  @ Wo2, epilogue: o2 = PW0*C
// Weights transposed [w][u] pad 68 (conflict-free LDS.128).
// Acts in [m][u] planes (warp-broadcast loads).
// ===========================================================================
#define B_RT 32
#define B_SWA 0                       // 128*68 = 8704
#define B_SWB (B_SWA + 128*68)        // 8704
#define B_SWC (B_SWB + 128*68)        // 64*68 = 4352
#define B_SSA (B_SWC + 64*68)         // 32*64 = 2048
#define B_SVB (B_SSA + 32*64)         // 96*64 = 6144
#define B_SCR (B_SVB + 96*64)         // 96*64 = 6144
#define B_SA  (B_SCR + 96*64)         // 32*128 = 4096
#define B_SI2 (B_SA + 32*128)         // 128
#define B_SMEM_FLOATS (B_SI2 + B_RT*4)
#define B_SMEM_BYTES  (B_SMEM_FLOATS * 4)

__global__ __launch_bounds__(512, 1) void k_o12(
    const float* __restrict__ in1, const float* __restrict__ in2,
    const float* __restrict__ Wa1, const float* __restrict__ Wb0,
    const float* __restrict__ Wo2, float* __restrict__ out,
    int n, int nChunks)
{
    extern __shared__ float sm[];
    float* sWaT = sm + B_SWA;
    float* sWbT = sm + B_SWB;
    float* sWcT = sm + B_SWC;
    float* sSa  = sm + B_SSA;
    float* sVb  = sm + B_SVB;
    float* sCr  = sm + B_SCR;
    float* sA   = sm + B_SA;
    float* sI2  = sm + B_SI2;

    const int tid = threadIdx.x;

    // Stage weights transposed [w][u] pad 68
    for (int idx = tid; idx < 64 * 128; idx += 512) {
        int u = idx >> 7, w = idx & 127;
        sWaT[w * 68 + u] = Wa1[idx];
        sWbT[w * 68 + u] = Wb0[idx];
    }
    for (int idx = tid; idx < 64 * 64; idx += 512) {
        int u = idx >> 6, w = idx & 63;
        sWcT[w * 68 + u] = Wo2[idx];
    }

    const int tx = tid & 31;
    const int ty = tid >> 5;   // [0,16)

    for (int chunk = blockIdx.x; chunk < nChunks; chunk += gridDim.x) {
        const int row0 = chunk * B_RT;
        __syncthreads();

        if (tid < B_RT * 4) {
            int r = tid >> 2, c = tid & 3;
            int nr = row0 + r;
            sI2[tid] = (nr < n) ? in2[nr * 4 + c] : 0.f;
        }
        __syncthreads();

        // Stage activation planes
        {
            const int u  = tid & 63;
            const int rb = tid >> 6;
            #pragma unroll
            for (int i = 0; i < 4; i++) {
                int r  = rb + 8 * i;
                int nr = row0 + r;
                if (nr < n) {
                    const float* ip = in1 + (size_t)nr * 256;
                    float vx = sI2[r*4+1], vy = sI2[r*4+2], vz = sI2[r*4+3];
                    float b0 = ip[64 + 3*u], b1 = ip[65 + 3*u], b2 = ip[66 + 3*u];
                    sSa[r*64 + u] = ip[u];
                    sVb[(r*3 + 0)*64 + u] = b0;
                    sVb[(r*3 + 1)*64 + u] = b1;
                    sVb[(r*3 + 2)*64 + u] = b2;
                    sCr[(r*3 + 0)*64 + u] = b1*vz - b2*vy;
                    sCr[(r*3 + 1)*64 + u] = b2*vx - b0*vz;
                    sCr[(r*3 + 2)*64 + u] = b0*vy - b1*vx;
                } else {
                    sSa[r*64 + u] = 0.f;
                    #pragma unroll
                    for (int k = 0; k < 3; k++) {
                        sVb[(r*3 + k)*64 + u] = 0.f;
                        sCr[(r*3 + k)*64 + u] = 0.f;
                    }
                }
            }
        }
        __syncthreads();

        // ---- G1: A = sa @ Wa1.  M=32 (R=2), C=4 ----
        {
            u64t acc[2][4];
            #pragma unroll
            for (int ri = 0; ri < 2; ri++)
                #pragma unroll
                for (int c = 0; c < 4; c++) acc[ri][c] = 0ull;

            #pragma unroll 2
            for (int u = 0; u < 64; u += 4) {
                ulonglong2 w[4];
                #pragma unroll
                for (int c = 0; c < 4; c++)
                    w[c] = *reinterpret_cast<const ulonglong2*>(sWaT + (tx + 32*c) * 68 + u);
                #pragma unroll
                for (int ri = 0; ri < 2; ri++) {
                    ulonglong2 a = *reinterpret_cast<const ulonglong2*>(sSa + (ty*2 + ri) * 64 + u);
                    #pragma unroll
                    for (int c = 0; c < 4; c++) {
                        acc[ri][c] = ffma2(a.x, w[c].x, acc[ri][c]);
                        acc[ri][c] = ffma2(a.y, w[c].y, acc[ri][c]);
                    }
                }
            }
            #pragma unroll
            for (int ri = 0; ri < 2; ri++)
                #pragma unroll
                for (int c = 0; c < 4; c++)
                    sA[(ty*2 + ri) * 128 + tx + 32*c] = hsum2(acc[ri][c]);
        }
        __syncthreads();

        // ---- G2: B = vb @ Wb0.  M=96 (R=6), C=4; fused o1 epilogue ----
        {
            u64t acc[6][4];
            #pragma unroll
            for (int ri = 0; ri < 6; ri++)
                #pragma unroll
                for (int c = 0; c < 4; c++) acc[ri][c] = 0ull;

            #pragma unroll 2
            for (int u = 0; u < 64; u += 4) {
                ulonglong2 w[4];
                #pragma unroll
                for (int c = 0; c < 4; c++)
                    w[c] = *reinterpret_cast<const ulonglong2*>(sWbT + (tx + 32*c) * 68 + u);
                #pragma unroll
                for (int ri = 0; ri < 6; ri++) {
                    ulonglong2 a = *reinterpret_cast<const ulonglong2*>(sVb + (ty*6 + ri) * 64 + u);
                    #pragma unroll
                    for (int c = 0; c < 4; c++) {
                        acc[ri][c] = ffma2(a.x, w[c].x, acc[ri][c]);
                        acc[ri][c] = ffma2(a.y, w[c].y, acc[ri][c]);
                    }
                }
            }
            #pragma unroll
            for (int ri = 0; ri < 6; ri++) {
                int m = ty*6 + ri;
                int r = m / 3, k = m - r * 3;
                int nr = row0 + r;
                if (nr >= n) continue;
                float s0  = sI2[r*4 + 0];
                float v1k = sI2[r*4 + 1 + k];
                float* op = out + (size_t)nr * OUT_STRIDE + 320;
                #pragma unroll
                for (int c = 0; c < 4; c++) {
                    int w = tx + 32*c;
                    float Aval = sA[r*128 + w];
                    op[3*w + k] = PW0f * (Aval * v1k + hsum2(acc[ri][c]) * s0);
                }
            }
        }

        // ---- G3: C = cr @ Wo2.  M=96 (R=6), C=2; o2 epilogue ----
        {
            u64t acc[6][2];
            #pragma unroll
            for (int ri = 0; ri < 6; ri++)
                #pragma unroll
                for (int c = 0; c < 2; c++) acc[ri][c] = 0ull;

            #pragma unroll 2
            for (int u = 0; u < 64; u += 4) {
                ulonglong2 w[2];
                #pragma unroll
                for (int c = 0; c < 2; c++)
                    w[c] = *reinterpret_cast<const ulonglong2*>(sWcT + (tx + 32*c) * 68 + u);
                #pragma unroll
                for (int ri = 0; ri < 6; ri++) {
                    ulonglong2 a = *reinterpret_cast<const ulonglong2*>(sCr + (ty*6 + ri) * 64 + u);
                    #pragma unroll
                    for (int c = 0; c < 2; c++) {
                        acc[ri][c] = ffma2(a.x, w[c].x, acc[ri][c]);
                        acc[ri][c] = ffma2(a.y, w[c].y, acc[ri][c]);
                    }
                }
            }
            #pragma unroll
            for (int ri = 0; ri < 6; ri++) {
                int m = ty*6 + ri;
                int r = m / 3, k = m - r * 3;
                int nr = row0 + r;
                if (nr >= n) continue;
                float* op = out + (size_t)nr * OUT_STRIDE + 704;
                #pragma unroll
                for (int c = 0; c < 2; c++) {
                    int w = tx + 32*c;
                    op[3*w + k] = PW0f * hsum2(acc[ri][c]);
                }
            }
        }
    }
}

extern "C" void kernel_launch(void* const* d_in, const int* in_sizes, int n_in,
                              void* d_out, int out_size)
{
    const float* in1   = (const float*)d_in[0];
    const float* in2   = (const float*)d_in[1];
    const float* Wa0   = (const float*)d_in[2];
    const float* Wb1o0 = (const float*)d_in[3];
    const float* Wa1   = (const float*)d_in[4];
    const float* Wb0   = (const float*)d_in[5];
    const float* Wo2   = (const float*)d_in[6];
    const float* bias  = (const float*)d_in[7];
    float* out = (float*)d_out;

    const int n = in_sizes[0] / 256;

    cudaFuncSetAttribute(k_o0,  cudaFuncAttributeMaxDynamicSharedMemorySize, A_SMEM_BYTES);
    cudaFuncSetAttribute(k_o12, cudaFuncAttributeMaxDynamicSharedMemorySize, B_SMEM_BYTES);

    int sms = 148;
    cudaDeviceGetAttribute(&sms, cudaDevAttrMultiProcessorCount, 0);

    const int chA = (n + A_RT - 1) / A_RT;
    const int chB = (n + B_RT - 1) / B_RT;
    const int gA = sms < chA ? sms : chA;
    const int gB = sms < chB ? sms : chB;

    k_o12<<<gB, 512, B_SMEM_BYTES>>>(in1, in2, Wa1, Wb0, Wo2, out, n, chB);
    k_o0 <<<gA, 512, A_SMEM_BYTES>>>(in1, in2, Wa0, Wb1o0, bias, out, n, chA);
}

// round 5
// speedup vs baseline: 1.7897x; 1.7897x over previous
#include <cuda_runtime.h>
#include <cuda_bf16.h>
#include <cstdint>

#define PW0f 0.08838834764831845f
#define INV_SQRT3f 0.5773502691896258f
#define OUT_STRIDE 896

// ---------------- helpers ----------------
__device__ __forceinline__ uint32_t smem_u32(const void* p) {
    uint32_t a;
    asm("{ .reg .u64 t; cvta.to.shared.u64 t, %1; cvt.u32.u64 %0, t; }" : "=r"(a) : "l"(p));
    return a;
}

__device__ __forceinline__ void ldsm4(uint32_t addr, uint32_t& r0, uint32_t& r1,
                                      uint32_t& r2, uint32_t& r3) {
    asm volatile("ldmatrix.sync.aligned.m8n8.x4.shared.b16 {%0,%1,%2,%3}, [%4];"
                 : "=r"(r0), "=r"(r1), "=r"(r2), "=r"(r3) : "r"(addr));
}

__device__ __forceinline__ void mma16816(float* d, const uint32_t* a,
                                         uint32_t b0, uint32_t b1) {
    asm volatile("mma.sync.aligned.m16n8k16.row.col.f32.bf16.bf16.f32 "
                 "{%0,%1,%2,%3}, {%4,%5,%6,%7}, {%8,%9}, {%0,%1,%2,%3};"
                 : "+f"(d[0]), "+f"(d[1]), "+f"(d[2]), "+f"(d[3])
                 : "r"(a[0]), "r"(a[1]), "r"(a[2]), "r"(a[3]), "r"(b0), "r"(b1));
}

__device__ __forceinline__ void bsplit(float f, unsigned short& h, unsigned short& l) {
    __nv_bfloat16 hb = __float2bfloat16(f);
    __nv_bfloat16 lb = __float2bfloat16(f - __bfloat162float(hb));
    h = __bfloat16_as_ushort(hb);
    l = __bfloat16_as_ushort(lb);
}
__device__ __forceinline__ void packsplit2(float f0, float f1, uint32_t& hp, uint32_t& lp) {
    unsigned short h0, l0, h1, l1;
    bsplit(f0, h0, l0); bsplit(f1, h1, l1);
    hp = (uint32_t)h0 | ((uint32_t)h1 << 16);
    lp = (uint32_t)l0 | ((uint32_t)l1 << 16);
}

// ===========================================================================
// Kernel A: o0 (cols 0..319).  Chunk 64 rows.
//   L[64][128] = [sa*s0 | dot(vb,v1)]  (hi/lo bf16)
//   W[320][128] (transposed, hi/lo, PW0 folded; Wb1 also /sqrt3), pitch 136 bf16
//   16 warps: 4 m-tiles x 4 n-groups of 80 cols (10 ntiles), 3-pass split MMA.
// ===========================================================================
#define A_RT 64
#define AO_WH   0
#define AO_WL   87040
#define AO_AH   174080
#define AO_AL   191488
#define AO_BIAS 208896
#define A_SMEM  210176

__global__ __launch_bounds__(512, 1) void k_o0(
    const float* __restrict__ in1, const float* __restrict__ in2,
    const float* __restrict__ Wa0, const float* __restrict__ Wb1,
    const float* __restrict__ bias, float* __restrict__ out,
    int n, int nChunks)
{
    extern __shared__ char sm[];
    const uint32_t sb = smem_u32(sm);
    const int tid = threadIdx.x, lane = tid & 31, wid = tid >> 5;
    const int wm = wid & 3, wn = wid >> 2;

    // stage weights (transposed [n][k], pitch 272B)
    for (int idx = tid; idx < 64 * 320; idx += 512) {
        int u = idx / 320, col = idx - u * 320;
        unsigned short h, l;
        bsplit(PW0f * Wa0[idx], h, l);
        *(unsigned short*)(sm + AO_WH + col * 272 + 2 * u) = h;
        *(unsigned short*)(sm + AO_WL + col * 272 + 2 * u) = l;
        bsplit(PW0f * INV_SQRT3f * Wb1[idx], h, l);
        *(unsigned short*)(sm + AO_WH + col * 272 + 128 + 2 * u) = h;
        *(unsigned short*)(sm + AO_WL + col * 272 + 128 + 2 * u) = l;
    }
    for (int i = tid; i < 320; i += 512) ((float*)(sm + AO_BIAS))[i] = bias[i];

    // ldmatrix addresses
    const uint32_t aOffH = sb + AO_AH + (uint32_t)(wm * 16 + (lane & 15)) * 272 + (lane >> 4) * 16;
    const uint32_t aOffL = aOffH + (AO_AL - AO_AH);
    const int wlr = (lane & 7) + ((lane >> 4) & 1) * 8;
    const int wkh = (lane >> 3) & 1;
    const uint32_t wOffH = sb + AO_WH + (uint32_t)(wn * 80 + wlr) * 272 + wkh * 16;
    const uint32_t wOffL = wOffH + (AO_WL - AO_WH);

    const int r = tid >> 3, p = tid & 7;

    for (int chunk = blockIdx.x; chunk < nChunks; chunk += gridDim.x) {
        const int row0 = chunk * A_RT;
        __syncthreads();

        // stage activations (hi/lo bf16)
        {
            int nr = row0 + r;
            char* rowH = sm + AO_AH + r * 272;
            char* rowL = sm + AO_AL + r * 272;
            if (nr < n) {
                const float* ip = in1 + (size_t)nr * 256;
                float4 iv = *(const float4*)(in2 + (size_t)nr * 4);
                if (p < 4) {
                    int k0 = p * 16;
                    #pragma unroll
                    for (int i = 0; i < 16; i += 2) {
                        uint32_t hp, lp;
                        packsplit2(ip[k0+i] * iv.x, ip[k0+i+1] * iv.x, hp, lp);
                        *(uint32_t*)(rowH + 2*(k0+i)) = hp;
                        *(uint32_t*)(rowL + 2*(k0+i)) = lp;
                    }
                } else {
                    int j0 = (p - 4) * 16;
                    const float* vp = ip + 64;
                    #pragma unroll
                    for (int i = 0; i < 16; i += 2) {
                        int j = j0 + i;
                        float d0 = vp[3*j]*iv.y   + vp[3*j+1]*iv.z + vp[3*j+2]*iv.w;
                        float d1 = vp[3*j+3]*iv.y + vp[3*j+4]*iv.z + vp[3*j+5]*iv.w;
                        uint32_t hp, lp;
                        packsplit2(d0, d1, hp, lp);
                        *(uint32_t*)(rowH + 2*(64+j)) = hp;
                        *(uint32_t*)(rowL + 2*(64+j)) = lp;
                    }
                }
            } else {
                int k0 = (p < 4) ? p * 16 : 64 + (p - 4) * 16;
                #pragma unroll
                for (int i = 0; i < 16; i += 2) {
                    *(uint32_t*)(rowH + 2*(k0+i)) = 0u;
                    *(uint32_t*)(rowL + 2*(k0+i)) = 0u;
                }
            }
        }
        __syncthreads();

        float d[10][4];
        #pragma unroll
        for (int t = 0; t < 10; t++)
            #pragma unroll
            for (int q = 0; q < 4; q++) d[t][q] = 0.f;

        #pragma unroll 2
        for (int ks = 0; ks < 8; ks++) {
            uint32_t ah[4], al[4];
            ldsm4(aOffH + ks * 32, ah[0], ah[1], ah[2], ah[3]);
            ldsm4(aOffL + ks * 32, al[0], al[1], al[2], al[3]);
            #pragma unroll
            for (int ntp = 0; ntp < 5; ntp++) {
                uint32_t wh[4], wl[4];
                ldsm4(wOffH + ntp * 4352 + ks * 32, wh[0], wh[1], wh[2], wh[3]);
                ldsm4(wOffL + ntp * 4352 + ks * 32, wl[0], wl[1], wl[2], wl[3]);
                mma16816(d[2*ntp],   ah, wh[0], wh[1]);
                mma16816(d[2*ntp],   ah, wl[0], wl[1]);
                mma16816(d[2*ntp],   al, wh[0], wh[1]);
                mma16816(d[2*ntp+1], ah, wh[2], wh[3]);
                mma16816(d[2*ntp+1], ah, wl[2], wl[3]);
                mma16816(d[2*ntp+1], al, wh[2], wh[3]);
            }
        }

        // epilogue: registers -> gmem (32B-aligned float2)
        {
            const float* sBias = (const float*)(sm + AO_BIAS);
            int r0 = row0 + wm * 16 + (lane >> 2);
            int r1 = r0 + 8;
            int cb = wn * 80 + (lane & 3) * 2;
            #pragma unroll
            for (int nt = 0; nt < 10; nt++) {
                int col = cb + nt * 8;
                float b0 = sBias[col], b1 = sBias[col + 1];
                if (r0 < n) {
                    float2 v = { d[nt][0] + b0, d[nt][1] + b1 };
                    *(float2*)(out + (size_t)r0 * OUT_STRIDE + col) = v;
                }
                if (r1 < n) {
                    float2 v = { d[nt][2] + b0, d[nt][3] + b1 };
                    *(float2*)(out + (size_t)r1 * OUT_STRIDE + col) = v;
                }
            }
        }
    }
}

// ===========================================================================
// Kernel B: o1 (320..703), o2 (704..895).  Chunk 32 rows.
//   sA rows 0..31 = sa; rows 32..127 = vb flat m'=3r+k.  K=64, pitch 72 bf16.
//   G1 (warps 0-3):  sa @ Wa1'   -> sA1[32][132]
//   G2 (warps 4-15): vb @ [Wb0|Wo2]' -> sG2[96][196]
//   Epilogue: o1 = A1*v1 + B2*s0 ; o2 = (vb@Wo2) x v1  (PW0 folded)
// ===========================================================================
#define B_RT 32
#define BO_WA1H 0
#define BO_WA1L 18432
#define BO_WBCH 36864
#define BO_WBCL 64512
#define BO_AH   92160
#define BO_AL   110592
#define BO_A1   129024
#define BO_G2   145920
#define BO_I2   221184
#define B_SMEM  221696

__global__ __launch_bounds__(512, 1) void k_o12(
    const float* __restrict__ in1, const float* __restrict__ in2,
    const float* __restrict__ Wa1, const float* __restrict__ Wb0,
    const float* __restrict__ Wo2, float* __restrict__ out,
    int n, int nChunks)
{
    extern __shared__ char sm[];
    const uint32_t sb = smem_u32(sm);
    const int tid = threadIdx.x, lane = tid & 31, wid = tid >> 5;

    // stage weights [n][u], pitch 144B, PW0 folded
    for (int idx = tid; idx < 64 * 128; idx += 512) {
        int u = idx >> 7, w = idx & 127;
        unsigned short h, l;
        bsplit(PW0f * Wa1[idx], h, l);
        *(unsigned short*)(sm + BO_WA1H + w * 144 + 2 * u) = h;
        *(unsigned short*)(sm + BO_WA1L + w * 144 + 2 * u) = l;
    }
    for (int idx = tid; idx < 64 * 192; idx += 512) {
        int u = idx / 192, nn = idx - u * 192;
        float v = (nn < 128) ? Wb0[u * 128 + nn] : Wo2[u * 64 + (nn - 128)];
        unsigned short h, l;
        bsplit(PW0f * v, h, l);
        *(unsigned short*)(sm + BO_WBCH + nn * 144 + 2 * u) = h;
        *(unsigned short*)(sm + BO_WBCL + nn * 144 + 2 * u) = l;
    }

    const bool isG1 = (wid < 4);
    int wm, wn, rowbase, colH;
    if (isG1) { wm = wid & 1; wn = wid >> 1; rowbase = wm * 16; colH = BO_WA1H; }
    else      { int ix = wid - 4; wn = ix / 6; wm = ix - wn * 6; rowbase = 32 + wm * 16; colH = BO_WBCH; }
    const int colbase = isG1 ? wn * 64 : wn * 96;

    const uint32_t aOffH = sb + BO_AH + (uint32_t)(rowbase + (lane & 15)) * 144 + (lane >> 4) * 16;
    const uint32_t aOffL = aOffH + (BO_AL - BO_AH);
    const int wlr = (lane & 7) + ((lane >> 4) & 1) * 8;
    const int wkh = (lane >> 3) & 1;
    const uint32_t wOffH = sb + colH + (uint32_t)(colbase + wlr) * 144 + wkh * 16;
    const uint32_t wOffL = wOffH + 18432;   // (WA1L-WA1H) == (WBCL-WBCH) == 18432? no!

    // NOTE: WBCL - WBCH = 27648; recompute per branch:
    const uint32_t wLdelta = isG1 ? (BO_WA1L - BO_WA1H) : (BO_WBCL - BO_WBCH);
    const uint32_t wOffLo = wOffH + wLdelta;
    (void)wOffL;

    float* sA1f = (float*)(sm + BO_A1);
    float* sG2f = (float*)(sm + BO_G2);
    float* sI2  = (float*)(sm + BO_I2);

    const int r = tid >> 4, q = tid & 15;
    const int k1a[3] = {1, 2, 0}, k2a[3] = {2, 0, 1};

    for (int chunk = blockIdx.x; chunk < nChunks; chunk += gridDim.x) {
        const int row0 = chunk * B_RT;
        __syncthreads();

        if (tid < 128) {
            int rr = tid >> 2, cc = tid & 3;
            int nr = row0 + rr;
            sI2[tid] = (nr < n) ? in2[(size_t)nr * 4 + cc] : 0.f;
        }

        // stage A
        {
            int nr = row0 + r;
            if (nr < n) {
                const float* ip = in1 + (size_t)nr * 256;
                if (q < 4) {
                    int u0 = q * 16;
                    char* rowH = sm + BO_AH + r * 144;
                    char* rowL = sm + BO_AL + r * 144;
                    #pragma unroll
                    for (int i = 0; i < 16; i += 2) {
                        uint32_t hp, lp;
                        packsplit2(ip[u0+i], ip[u0+i+1], hp, lp);
                        *(uint32_t*)(rowH + 2*(u0+i)) = hp;
                        *(uint32_t*)(rowL + 2*(u0+i)) = lp;
                    }
                } else {
                    int v0 = (q - 4) * 16;
                    #pragma unroll
                    for (int i = 0; i < 16; i++) {
                        int v = v0 + i;
                        int u = v / 3, kk = v - 3 * u;
                        unsigned short h, l;
                        bsplit(ip[64 + v], h, l);
                        int rw = 32 + 3 * r + kk;
                        *(unsigned short*)(sm + BO_AH + rw * 144 + 2 * u) = h;
                        *(unsigned short*)(sm + BO_AL + rw * 144 + 2 * u) = l;
                    }
                }
            } else {
                if (q < 4) {
                    int u0 = q * 16;
                    #pragma unroll
                    for (int i = 0; i < 16; i += 2) {
                        *(uint32_t*)(sm + BO_AH + r * 144 + 2*(u0+i)) = 0u;
                        *(uint32_t*)(sm + BO_AL + r * 144 + 2*(u0+i)) = 0u;
                    }
                } else {
                    int v0 = (q - 4) * 16;
                    #pragma unroll
                    for (int i = 0; i < 16; i++) {
                        int v = v0 + i;
                        int u = v / 3, kk = v - 3 * u;
                        int rw = 32 + 3 * r + kk;
                        *(unsigned short*)(sm + BO_AH + rw * 144 + 2 * u) = 0;
                        *(unsigned short*)(sm + BO_AL + rw * 144 + 2 * u) = 0;
                    }
                }
            }
        }
        __syncthreads();

        if (isG1) {
            float d[8][4];
            #pragma unroll
            for (int t = 0; t < 8; t++)
                #pragma unroll
                for (int z = 0; z < 4; z++) d[t][z] = 0.f;
            #pragma unroll 2
            for (int ks = 0; ks < 4; ks++) {
                uint32_t ah[4], al[4];
                ldsm4(aOffH + ks * 32, ah[0], ah[1], ah[2], ah[3]);
                ldsm4(aOffL + ks * 32, al[0], al[1], al[2], al[3]);
                #pragma unroll
                for (int ntp = 0; ntp < 4; ntp++) {
                    uint32_t wh[4], wl[4];
                    ldsm4(wOffH  + ntp * 2304 + ks * 32, wh[0], wh[1], wh[2], wh[3]);
                    ldsm4(wOffLo + ntp * 2304 + ks * 32, wl[0], wl[1], wl[2], wl[3]);
                    mma16816(d[2*ntp],   ah, wh[0], wh[1]);
                    mma16816(d[2*ntp],   ah, wl[0], wl[1]);
                    mma16816(d[2*ntp],   al, wh[0], wh[1]);
                    mma16816(d[2*ntp+1], ah, wh[2], wh[3]);
                    mma16816(d[2*ntp+1], ah, wl[2], wl[3]);
                    mma16816(d[2*ntp+1], al, wh[2], wh[3]);
                }
            }
            int m0 = wm * 16 + (lane >> 2);
            #pragma unroll
            for (int nt = 0; nt < 8; nt++) {
                int c = wn * 64 + nt * 8 + (lane & 3) * 2;
                sA1f[m0 * 132 + c]           = d[nt][0];
                sA1f[m0 * 132 + c + 1]       = d[nt][1];
                sA1f[(m0 + 8) * 132 + c]     = d[nt][2];
                sA1f[(m0 + 8) * 132 + c + 1] = d[nt][3];
            }
        } else {
            float d[12][4];
            #pragma unroll
            for (int t = 0; t < 12; t++)
                #pragma unroll
                for (int z = 0; z < 4; z++) d[t][z] = 0.f;
            #pragma unroll 2
            for (int ks = 0; ks < 4; ks++) {
                uint32_t ah[4], al[4];
                ldsm4(aOffH + ks * 32, ah[0], ah[1], ah[2], ah[3]);
                ldsm4(aOffL + ks * 32, al[0], al[1], al[2], al[3]);
                #pragma unroll
                for (int ntp = 0; ntp < 6; ntp++) {
                    uint32_t wh[4], wl[4];
                    ldsm4(wOffH  + ntp * 2304 + ks * 32, wh[0], wh[1], wh[2], wh[3]);
                    ldsm4(wOffLo + ntp * 2304 + ks * 32, wl[0], wl[1], wl[2], wl[3]);
                    mma16816(d[2*ntp],   ah, wh[0], wh[1]);
                    mma16816(d[2*ntp],   ah, wl[0], wl[1]);
                    mma16816(d[2*ntp],   al, wh[0], wh[1]);
                    mma16816(d[2*ntp+1], ah, wh[2], wh[3]);
                    mma16816(d[2*ntp+1], ah, wl[2], wl[3]);
                    mma16816(d[2*ntp+1], al, wh[2], wh[3]);
                }
            }
            int m0 = wm * 16 + (lane >> 2);
            #pragma unroll
            for (int nt = 0; nt < 12; nt++) {
                int c = wn * 96 + nt * 8 + (lane & 3) * 2;
                sG2f[m0 * 196 + c]           = d[nt][0];
                sG2f[m0 * 196 + c + 1]       = d[nt][1];
                sG2f[(m0 + 8) * 196 + c]     = d[nt][2];
                sG2f[(m0 + 8) * 196 + c + 1] = d[nt][3];
            }
        }
        __syncthreads();

        // o1: 32 rows x 384 cols (coalesced)
        #pragma unroll
        for (int i = 0; i < 24; i++) {
            int g = tid + i * 512;
            int row = g / 384, c = g - row * 384;
            int w = c / 3, kk = c - 3 * w;
            int nr = row0 + row;
            if (nr < n) {
                float val = sA1f[row * 132 + w] * sI2[row * 4 + 1 + kk]
                          + sG2f[(3 * row + kk) * 196 + w] * sI2[row * 4];
                out[(size_t)nr * OUT_STRIDE + 320 + c] = val;
            }
        }
        // o2: 32 rows x 192 cols (coalesced)
        #pragma unroll
        for (int i = 0; i < 12; i++) {
            int g = tid + i * 512;
            int row = g / 192, c = g - row * 192;
            int w = c / 3, kk = c - 3 * w;
            int nr = row0 + row;
            if (nr < n) {
                int k1 = k1a[kk], k2 = k2a[kk];
                float val = sG2f[(3 * row + k1) * 196 + 128 + w] * sI2[row * 4 + 1 + k2]
                          - sG2f[(3 * row + k2) * 196 + 128 + w] * sI2[row * 4 + 1 + k1];
                out[(size_t)nr * OUT_STRIDE + 704 + c] = val;
            }
        }
    }
}

extern "C" void kernel_launch(void* const* d_in, const int* in_sizes, int n_in,
                              void* d_out, int out_size)
{
    const float* in1   = (const float*)d_in[0];
    const float* in2   = (const float*)d_in[1];
    const float* Wa0   = (const float*)d_in[2];
    const float* Wb1o0 = (const float*)d_in[3];
    const float* Wa1   = (const float*)d_in[4];
    const float* Wb0   = (const float*)d_in[5];
    const float* Wo2   = (const float*)d_in[6];
    const float* bias  = (const float*)d_in[7];
    float* out = (float*)d_out;

    const int n = in_sizes[0] / 256;

    cudaFuncSetAttribute(k_o0,  cudaFuncAttributeMaxDynamicSharedMemorySize, A_SMEM);
    cudaFuncSetAttribute(k_o12, cudaFuncAttributeMaxDynamicSharedMemorySize, B_SMEM);

    int sms = 148;
    cudaDeviceGetAttribute(&sms, cudaDevAttrMultiProcessorCount, 0);

    const int chA = (n + A_RT - 1) / A_RT;
    const int chB = (n + B_RT - 1) / B_RT;
    const int gA = sms < chA ? sms : chA;
    const int gB = sms < chB ? sms : chB;

    k_o12<<<gB, 512, B_SMEM>>>(in1, in2, Wa1, Wb0, Wo2, out, n, chB);
    k_o0 <<<gA, 512, A_SMEM>>>(in1, in2, Wa0, Wb1o0, bias, out, n, chA);
}